// round 9
// baseline (speedup 1.0000x reference)
#include <cuda_runtime.h>
#include <cuda_bf16.h>

// ---------------------------------------------------------------------------
// GraphLogitLayers: conv3x3(circular)+relu+mean-pool -> edge MLP -> node MLP.
// P=4, B=128, C=32, H=W=64, HID=64. NIMG = 512.
// Conv: 1-D Winograd F(2,3) along W (1.5x MAC reduction) on bf16 mma.sync.
//   V = B^T d = [d0-d2, d1+d2, d2-d1, d1-d3] computed in smem (FFMA pipe),
//   U = Gw pre-transformed in prep, 4 point-GEMMs with K = 3kh x 32ic = 96,
//   inverse transform A^T M = [m0+m1+m2, m1-m2-m3] thread-local in epilogue,
//   fused bias+relu+pool partials. MMA floor ~189us (vs 284us direct).
// MLP: R7 version verbatim (measured 21.1us).
// ---------------------------------------------------------------------------

#define NIMG   512
#define CIN    32
#define COUT   64
#define HID    64
#define NSLOT  64          // 32 row-pairs * 2 row-warpgroups

// device scratch (no allocations allowed)
__device__ alignas(16) float g_partial[NSLOT * NIMG * COUT];   // 8 MB
__device__ alignas(16) float g_nodes[NIMG * COUT];
__device__ alignas(16) uint4 g_wa[12 * 2 * 4 * 32];            // [t*3+kh][ks][mt][lane]

// ---------------------------------------------------------------------------
// prep: Winograd-transform conv weights (G w along kw) into mma A-fragment
// order. tap = t*3 + kh, t in 0..3:
//   U0=w0, U1=(w0+w1+w2)/2, U2=(w0-w1+w2)/2, U3=w2.
// Fragment: reg rr of lane l for (tap, ks, mt):
//   m = mt*16 + (rr&1)*8 + (l>>2),  ic = ks*16 + (rr>>1)*8 + 2*(l&3) (+1 hi)
// ---------------------------------------------------------------------------
__global__ void prep_kernel(const float* __restrict__ w) {
    int i = blockIdx.x * blockDim.x + threadIdx.x;
    if (i >= 3072) return;
    int lane = i & 31;
    int mt   = (i >> 5) & 3;
    int ks   = (i >> 7) & 1;
    int tap  = i >> 8;           // 0..11
    int t    = tap / 3;
    int kh   = tap % 3;
    unsigned r[4];
#pragma unroll
    for (int rr = 0; rr < 4; rr++) {
        int m  = mt * 16 + ((rr & 1) << 3) + (lane >> 2);
        int k0 = ks * 16 + ((rr >> 1) << 3) + ((lane & 3) << 1);
        unsigned pk = 0;
#pragma unroll
        for (int half = 0; half < 2; half++) {
            int ic = k0 + half;
            const float* wp = w + ((m * CIN + ic) * 3 + kh) * 3;
            float w0 = wp[0], w1 = wp[1], w2 = wp[2];
            float val = (t == 0) ? w0
                      : (t == 1) ? 0.5f * (w0 + w1 + w2)
                      : (t == 2) ? 0.5f * (w0 - w1 + w2)
                                 : w2;
            pk |= (unsigned)__bfloat16_as_ushort(__float2bfloat16(val)) << (half * 16);
        }
        r[rr] = pk;
    }
    g_wa[i] = make_uint4(r[0], r[1], r[2], r[3]);
}

// ---------------------------------------------------------------------------
__device__ __forceinline__ void mma_bf16(float* c, const unsigned* a,
                                         unsigned b0, unsigned b1) {
    asm volatile(
        "mma.sync.aligned.m16n8k16.row.col.f32.bf16.bf16.f32 "
        "{%0,%1,%2,%3}, {%4,%5,%6,%7}, {%8,%9}, {%0,%1,%2,%3};\n"
        : "+f"(c[0]), "+f"(c[1]), "+f"(c[2]), "+f"(c[3])
        : "r"(a[0]), "r"(a[1]), "r"(a[2]), "r"(a[3]), "r"(b0), "r"(b1));
}

__device__ __forceinline__ void ldsm_x4(unsigned& r0, unsigned& r1,
                                        unsigned& r2, unsigned& r3, unsigned addr) {
    asm volatile("ldmatrix.sync.aligned.m8n8.x4.shared.b16 {%0,%1,%2,%3}, [%4];\n"
                 : "=r"(r0), "=r"(r1), "=r"(r2), "=r"(r3) : "r"(addr));
}

// ---------------------------------------------------------------------------
// Winograd conv + bias + relu + spatial partial-sum.
// Grid (32 row-pairs, 512 imgs), 256 threads (8 warps = 2 rowg x 4 ocg).
// Per CTA: output rows r0, r0+1; input rows r0-1..r0+2 (circular).
// Dyn smem: raw bf16 [4 rows][66 cols(halo)][32 ic] at 0 (16896 B);
//           V bf16 [4 t][4 rows][32 wtiles][40 icpad] at 16896 (40960 B).
// Warp: 16 oc x 32 wtiles (one output row); per (kh,t): 2 A-frag uint4 +
// 4 ldsm.x4 + 8 mma. acc[t][ng][4] = 64 f32.
// ---------------------------------------------------------------------------
#define VOFF    16896
#define DYN_CONV 57856

__global__ __launch_bounds__(256, 2)
void conv_pool_kernel(const float* __restrict__ x, const float* __restrict__ conv_b) {
    extern __shared__ __align__(16) char dynsm[];
    __nv_bfloat16* raw = (__nv_bfloat16*)dynsm;            // [4][66][32]
    __nv_bfloat16* vv  = (__nv_bfloat16*)(dynsm + VOFF);   // elems: t*5120+rr*1280+wt*40+ic

    const int n   = blockIdx.y;
    const int rt  = blockIdx.x;
    const int r0  = rt * 2;
    const int tid = threadIdx.x;
    const float* xb = x + ((long)n << 17);

    // ---- stage raw input (bf16), 4 circular rows, halo cols ----
    for (int idx = tid; idx < 4 * CIN * 64; idx += 256) {
        int w    = idx & 63;
        int rest = idx >> 6;
        int ic   = rest & 31;
        int rr   = rest >> 5;
        int gh   = (r0 + rr + 63) & 63;
        raw[(rr * 66 + w + 1) * 32 + ic] =
            __float2bfloat16(xb[(ic << 12) + (gh << 6) + w]);
    }
    for (int idx = tid; idx < 4 * CIN * 2; idx += 256) {
        int side = idx & 1;
        int rest = idx >> 1;
        int ic   = rest & 31;
        int rr   = rest >> 5;
        int gh   = (r0 + rr + 63) & 63;
        int gw   = side ? 0 : 63;
        int c    = side ? 65 : 0;
        raw[(rr * 66 + c) * 32 + ic] =
            __float2bfloat16(xb[(ic << 12) + (gh << 6) + gw]);
    }
    __syncthreads();

    // ---- Winograd input transform: V = [d0-d2, d1+d2, d2-d1, d1-d3] ----
    for (int u = tid; u < 4 * 32 * 32; u += 256) {
        int ic = u & 31;
        int wt = (u >> 5) & 31;
        int rr = u >> 10;
        int cb = (rr * 66 + 2 * wt) * 32 + ic;     // staged col 2wt = x[2wt-1]
        float d0 = __bfloat162float(raw[cb]);
        float d1 = __bfloat162float(raw[cb + 32]);
        float d2 = __bfloat162float(raw[cb + 64]);
        float d3 = __bfloat162float(raw[cb + 96]);
        int vb = rr * 1280 + wt * 40 + ic;
        vv[vb        ] = __float2bfloat16(d0 - d2);
        vv[vb +  5120] = __float2bfloat16(d1 + d2);
        vv[vb + 10240] = __float2bfloat16(d2 - d1);
        vv[vb + 15360] = __float2bfloat16(d1 - d3);
    }
    __syncthreads();

    // ---- 4 point-GEMMs (t), K = 3kh x 32ic ----
    const int lane = tid & 31;
    const int warp = tid >> 5;
    const int rowg = warp >> 2;     // 0..1 output row within pair
    const int ocg  = warp & 3;      // 0..3 oc group of 16

    unsigned lbase = (unsigned)__cvta_generic_to_shared(dynsm) + VOFF
                   + rowg * 2560 + (lane & 7) * 80 + ((lane >> 3) << 4);

    float acc[4][4][4];
#pragma unroll
    for (int t = 0; t < 4; t++)
#pragma unroll
        for (int ng = 0; ng < 4; ng++)
#pragma unroll
            for (int c = 0; c < 4; c++) acc[t][ng][c] = 0.f;

#pragma unroll
    for (int kh = 0; kh < 3; kh++) {
#pragma unroll
        for (int t = 0; t < 4; t++) {
            const int tap = t * 3 + kh;
            uint4 a0 = g_wa[((tap * 2 + 0) * 4 + ocg) * 32 + lane];
            uint4 a1 = g_wa[((tap * 2 + 1) * 4 + ocg) * 32 + lane];
            unsigned base = lbase + t * 10240 + kh * 2560;
#pragma unroll
            for (int ng = 0; ng < 4; ng++) {
                unsigned b0, b1, b2, b3;
                ldsm_x4(b0, b1, b2, b3, base + ng * 640);
                mma_bf16(acc[t][ng], (const unsigned*)&a0, b0, b1);
                mma_bf16(acc[t][ng], (const unsigned*)&a1, b2, b3);
            }
        }
    }

    // ---- inverse transform + bias + relu + pool ----
    const int grp = lane >> 2;
    const int tig = lane & 3;
    const int oc0 = ocg * 16 + grp;
    const int oc1 = oc0 + 8;
    const float bv0 = conv_b[oc0];
    const float bv1 = conv_b[oc1];
    float p0 = 0.f, p1 = 0.f;
#pragma unroll
    for (int ng = 0; ng < 4; ng++) {
#pragma unroll
        for (int c = 0; c < 2; c++) {
            float m0 = acc[0][ng][c], m1 = acc[1][ng][c];
            float m2 = acc[2][ng][c], m3 = acc[3][ng][c];
            p0 += fmaxf(m0 + m1 + m2 + bv0, 0.f) + fmaxf(m1 - m2 - m3 + bv0, 0.f);
            float M0 = acc[0][ng][c + 2], M1 = acc[1][ng][c + 2];
            float M2 = acc[2][ng][c + 2], M3 = acc[3][ng][c + 2];
            p1 += fmaxf(M0 + M1 + M2 + bv1, 0.f) + fmaxf(M1 - M2 - M3 + bv1, 0.f);
        }
    }
    p0 += __shfl_xor_sync(0xffffffffu, p0, 1);
    p0 += __shfl_xor_sync(0xffffffffu, p0, 2);
    p1 += __shfl_xor_sync(0xffffffffu, p1, 1);
    p1 += __shfl_xor_sync(0xffffffffu, p1, 2);
    if (tig == 0) {
        int slot = rt * 2 + rowg;                   // 0..63, unique writer
        g_partial[slot * (NIMG * COUT) + (n << 6) + oc0] = p0;
        g_partial[slot * (NIMG * COUT) + (n << 6) + oc1] = p1;
    }
}

// ---------------------------------------------------------------------------
__global__ void reduce_nodes_kernel() {
    int i = blockIdx.x * blockDim.x + threadIdx.x;   // 32768
    float s = 0.f;
#pragma unroll
    for (int k = 0; k < NSLOT; k++) s += g_partial[k * (NIMG * COUT) + i];
    g_nodes[i] = s * (1.f / 4096.f);
}

// ---------------------------------------------------------------------------
// Graph MLP: R7 version verbatim. 32 blocks x 1024 threads; 4 batches/block
// share one smem weight staging; rank-1 edge decomposition.
// ---------------------------------------------------------------------------
#define MLP_SLAB 2064
#define MLP_DYN  ((16704 + 4 * MLP_SLAB) * 4)    // 99840 B

__global__ __launch_bounds__(1024)
void mlp_kernel(const float* __restrict__ e_w1, const float* __restrict__ e_b1,
                const float* __restrict__ e_w2, const float* __restrict__ e_b2,
                const float* __restrict__ o_w1, const float* __restrict__ o_b1,
                const float* __restrict__ o_w2, const float* __restrict__ o_b2,
                float* __restrict__ out) {
    extern __shared__ float ws[];
    float* W1  = ws;
    float* W2  = ws + 8192;
    float* OW1 = ws + 12288;
    float* OW2 = ws + 16384;
    float* B1  = ws + 16448;
    float* B2  = ws + 16512;
    float* OB1 = ws + 16576;

    const int tid  = threadIdx.x;
    const int bg   = tid >> 8;          // batch group 0..3
    const int t256 = tid & 255;
    const int g    = t256 >> 6;         // node 0..3
    const int h    = t256 & 63;
    const int b    = blockIdx.x * 4 + bg;

    float* slab = ws + 16704 + bg * MLP_SLAB;
    float* sN  = slab;
    float* sA  = slab + 256;
    float* sC  = slab + 512;
    float* sE  = slab + 768;    // [i][j][h] = [(i*4+j)*64+h]
    float* sM  = slab + 1792;
    float* red = slab + 2048;

    for (int i = tid; i < 8192; i += 1024) W1[i]  = e_w1[i];
    for (int i = tid; i < 4096; i += 1024) W2[i]  = e_w2[i];
    for (int i = tid; i < 4096; i += 1024) OW1[i] = o_w1[i];
    if (tid < 64) {
        OW2[tid] = o_w2[tid];
        B1[tid]  = e_b1[tid];
        B2[tid]  = e_b2[tid];
        OB1[tid] = o_b1[tid];
    }
    if (tid == 0) ws[16640] = o_b2[0];
    sN[g * 64 + h] = g_nodes[(g * 128 + b) * HID + h];
    __syncthreads();

    {
        float a0 = B1[h], a1 = 0.f, c0 = 0.f, c1 = 0.f;
#pragma unroll 8
        for (int k = 0; k < 64; k += 2) {
            float n0 = sN[g * 64 + k], n1 = sN[g * 64 + k + 1];
            a0 = fmaf(n0, W1[k * 64 + h], a0);
            a1 = fmaf(n1, W1[(k + 1) * 64 + h], a1);
            c0 = fmaf(n0, W1[(64 + k) * 64 + h], c0);
            c1 = fmaf(n1, W1[(64 + k + 1) * 64 + h], c1);
        }
        sA[g * 64 + h] = a0 + a1;
        sC[g * 64 + h] = c0 + c1;
    }
    __syncthreads();
    {
        float a = sA[g * 64 + h];
#pragma unroll
        for (int j = 0; j < 4; j++)
            sE[(g * 4 + j) * 64 + h] = fmaxf(a + sC[j * 64 + h], 0.f);
    }
    __syncthreads();
    {
        float m = 0.f;
        for (int i = 0; i < 4; i++) {
            float q0 = B2[h], q1 = 0.f;
            const float* e = sE + (i * 4 + g) * 64;
#pragma unroll 8
            for (int k = 0; k < 64; k += 2) {
                q0 = fmaf(e[k],     W2[k * 64 + h],       q0);
                q1 = fmaf(e[k + 1], W2[(k + 1) * 64 + h], q1);
            }
            m += fmaxf(q0 + q1, 0.f);
        }
        sM[g * 64 + h] = m * 0.25f;
    }
    __syncthreads();
    {
        float q0 = OB1[h], q1 = 0.f;
#pragma unroll 8
        for (int k = 0; k < 64; k += 2) {
            q0 = fmaf(sM[g * 64 + k],     OW1[k * 64 + h],       q0);
            q1 = fmaf(sM[g * 64 + k + 1], OW1[(k + 1) * 64 + h], q1);
        }
        float v = fmaxf(q0 + q1, 0.f) * OW2[h];
#pragma unroll
        for (int m = 16; m >= 1; m >>= 1) v += __shfl_xor_sync(0xffffffffu, v, m);
        if ((t256 & 31) == 0) red[t256 >> 5] = v;
    }
    __syncthreads();
    if (t256 < 4) out[b * 4 + t256] = red[2 * t256] + red[2 * t256 + 1] + ws[16640];
}

// ---------------------------------------------------------------------------
extern "C" void kernel_launch(void* const* d_in, const int* in_sizes, int n_in,
                              void* d_out, int out_size) {
    const float* x      = (const float*)d_in[0];
    const float* conv_w = (const float*)d_in[1];
    const float* conv_b = (const float*)d_in[2];
    const float* e_w1   = (const float*)d_in[3];
    const float* e_b1   = (const float*)d_in[4];
    const float* e_w2   = (const float*)d_in[5];
    const float* e_b2   = (const float*)d_in[6];
    const float* o_w1   = (const float*)d_in[7];
    const float* o_b1   = (const float*)d_in[8];
    const float* o_w2   = (const float*)d_in[9];
    const float* o_b2   = (const float*)d_in[10];
    float* out = (float*)d_out;

    // idempotent, every launch (no static guards per harness rules)
    cudaFuncSetAttribute(conv_pool_kernel,
                         cudaFuncAttributeMaxDynamicSharedMemorySize, DYN_CONV);
    cudaFuncSetAttribute(mlp_kernel,
                         cudaFuncAttributeMaxDynamicSharedMemorySize, MLP_DYN);

    prep_kernel<<<12, 256>>>(conv_w);

    dim3 grid(32, NIMG);
    conv_pool_kernel<<<grid, 256, DYN_CONV>>>(x, conv_b);

    reduce_nodes_kernel<<<(NIMG * COUT) / 256, 256>>>();

    mlp_kernel<<<32, 1024, MLP_DYN>>>(e_w1, e_b1, e_w2, e_b2,
                                      o_w1, o_b1, o_w2, o_b2, out);
}

// round 10
// speedup vs baseline: 1.6617x; 1.6617x over previous
#include <cuda_runtime.h>
#include <cuda_bf16.h>

// ---------------------------------------------------------------------------
// GraphLogitLayers: conv3x3(circular)+relu+mean-pool -> edge MLP -> node MLP.
// P=4, B=128, C=32, H=W=64, HID=64. NIMG = 512.
// NOTE: harness PTX virtual target is compute_103 (no 'a' feature) => tcgen05
// unavailable; mma.sync implicit-GEMM conv is the ceiling (~284us HMMA floor).
// Conv: implicit-GEMM bf16 mma.sync, ldmatrix B loads, fragment-packed A,
//       warp tile 32oc x 64sp, fused bias+relu+pool partials. (proven R3/R6)
// MLP:  32 blocks x 1024 threads, 4 batches/block sharing one smem weight
//       staging; rank-1 edge decomposition e1(i,j)=relu(a_i+c_j). (proven R7)
// Winograd F(2,3) tried in R9: net regression (B-reuse halved, 2x per-CTA
// overhead, scalar transform phase) + 4.8x worse rel_err -> reverted.
// ---------------------------------------------------------------------------

#define NIMG   512
#define CIN    32
#define WW     64
#define COUT   64
#define HID    64
#define NSLOT  64          // 16 row-tiles * 4 sp-warps

// device scratch (no allocations allowed)
__device__ alignas(16) float g_partial[NSLOT * NIMG * COUT];   // 8 MB
__device__ alignas(16) float g_nodes[NIMG * COUT];
__device__ alignas(16) uint4 g_wa[9 * 2 * 4 * 32];             // [tap][ks][mt][lane]

// ---------------------------------------------------------------------------
// prep: pack conv weights into mma A-fragment order (bf16x2 per reg, uint4 per
// lane): reg r of lane l for (tap, ks, mt):
//   m = mt*16 + (r&1)*8 + (l>>2),  k = ks*16 + (r>>1)*8 + 2*(l&3) (+1 hi half)
// ---------------------------------------------------------------------------
__global__ void prep_kernel(const float* __restrict__ w) {
    int i = blockIdx.x * blockDim.x + threadIdx.x;
    if (i >= 2304) return;
    int lane = i & 31;
    int mt   = (i >> 5) & 3;
    int ks   = (i >> 7) & 1;
    int tap  = i >> 8;
    int kh = tap / 3, kw = tap % 3;
    unsigned r[4];
#pragma unroll
    for (int rr = 0; rr < 4; rr++) {
        int m = mt * 16 + ((rr & 1) << 3) + (lane >> 2);
        int k = ks * 16 + ((rr >> 1) << 3) + ((lane & 3) << 1);
        unsigned lo = __bfloat16_as_ushort(__float2bfloat16(w[((m * CIN + k    ) * 3 + kh) * 3 + kw]));
        unsigned hi = __bfloat16_as_ushort(__float2bfloat16(w[((m * CIN + k + 1) * 3 + kh) * 3 + kw]));
        r[rr] = lo | (hi << 16);
    }
    g_wa[i] = make_uint4(r[0], r[1], r[2], r[3]);
}

// ---------------------------------------------------------------------------
__device__ __forceinline__ void mma_bf16(float* c, const unsigned* a,
                                         unsigned b0, unsigned b1) {
    asm volatile(
        "mma.sync.aligned.m16n8k16.row.col.f32.bf16.bf16.f32 "
        "{%0,%1,%2,%3}, {%4,%5,%6,%7}, {%8,%9}, {%0,%1,%2,%3};\n"
        : "+f"(c[0]), "+f"(c[1]), "+f"(c[2]), "+f"(c[3])
        : "r"(a[0]), "r"(a[1]), "r"(a[2]), "r"(a[3]), "r"(b0), "r"(b1));
}

__device__ __forceinline__ void ldsm_x4(unsigned& r0, unsigned& r1,
                                        unsigned& r2, unsigned& r3, unsigned addr) {
    asm volatile("ldmatrix.sync.aligned.m8n8.x4.shared.b16 {%0,%1,%2,%3}, [%4];\n"
                 : "=r"(r0), "=r"(r1), "=r"(r2), "=r"(r3) : "r"(addr));
}

// ---------------------------------------------------------------------------
// Fused conv + bias + relu + spatial partial-sum.  (proven)
// Grid (16 row-tiles, 512 imgs), 256 threads (8 warps).
// Block tile: 4 rows x 64 cols x 64 oc. Warp: 32 oc x 64 sp (one row).
// Smem: 6 rows x 66 cols (circular halo) x ic, ic padded to ICP=40.
// ---------------------------------------------------------------------------
#define ICP 40

__global__ __launch_bounds__(256, 2)
void conv_pool_kernel(const float* __restrict__ x, const float* __restrict__ conv_b) {
    __shared__ alignas(16) __nv_bfloat16 tile[6 * 66 * ICP];   // 31680 B

    const int n   = blockIdx.y;
    const int rt  = blockIdx.x;
    const int h0  = rt * 4;
    const int tid = threadIdx.x;
    const float* xb = x + ((long)n << 17);

    // interior columns
    for (int idx = tid; idx < 6 * CIN * WW; idx += 256) {
        int w    = idx & 63;
        int rest = idx >> 6;
        int ic   = rest & 31;
        int rr   = rest >> 5;
        int gh   = (h0 + rr + 63) & 63;
        tile[(rr * 66 + w + 1) * ICP + ic] =
            __float2bfloat16(xb[(ic << 12) + (gh << 6) + w]);
    }
    // circular halo columns
    for (int idx = tid; idx < 6 * CIN * 2; idx += 256) {
        int side = idx & 1;
        int rest = idx >> 1;
        int ic   = rest & 31;
        int rr   = rest >> 5;
        int gh   = (h0 + rr + 63) & 63;
        int gw   = side ? 0 : 63;
        int c    = side ? 65 : 0;
        tile[(rr * 66 + c) * ICP + ic] =
            __float2bfloat16(xb[(ic << 12) + (gh << 6) + gw]);
    }
    __syncthreads();

    const int lane   = tid & 31;
    const int warp   = tid >> 5;
    const int warpOc = warp & 1;     // 2 oc groups of 32
    const int warpSp = warp >> 1;    // 4 sp groups = block-tile rows

    unsigned sbase = (unsigned)__cvta_generic_to_shared(tile) +
                     (((warpSp * 66 + (lane & 7)) * ICP + ((lane >> 3) << 3)) << 1);

    float acc[8][2][4];
#pragma unroll
    for (int nt = 0; nt < 8; nt++)
#pragma unroll
        for (int mt = 0; mt < 2; mt++)
#pragma unroll
            for (int c = 0; c < 4; c++) acc[nt][mt][c] = 0.f;

    for (int kh = 0; kh < 3; kh++) {
        for (int kw = 0; kw < 3; kw++) {
            const int tap = kh * 3 + kw;
            uint4 a00 = g_wa[((tap * 2 + 0) * 4 + warpOc * 2 + 0) * 32 + lane];
            uint4 a01 = g_wa[((tap * 2 + 0) * 4 + warpOc * 2 + 1) * 32 + lane];
            uint4 a10 = g_wa[((tap * 2 + 1) * 4 + warpOc * 2 + 0) * 32 + lane];
            uint4 a11 = g_wa[((tap * 2 + 1) * 4 + warpOc * 2 + 1) * 32 + lane];
            unsigned tapaddr = sbase + (unsigned)(((kh * 66 + kw) * ICP) << 1);
#pragma unroll
            for (int nt = 0; nt < 8; nt++) {
                unsigned b0, b1, b2, b3;
                ldsm_x4(b0, b1, b2, b3, tapaddr + nt * (8 * ICP * 2));
                mma_bf16(acc[nt][0], (const unsigned*)&a00, b0, b1);
                mma_bf16(acc[nt][1], (const unsigned*)&a01, b0, b1);
                mma_bf16(acc[nt][0], (const unsigned*)&a10, b2, b3);
                mma_bf16(acc[nt][1], (const unsigned*)&a11, b2, b3);
            }
        }
    }

    // epilogue: bias + relu + sum over spatial, reduce over (lane&3)
    const int rowa = lane >> 2;
#pragma unroll
    for (int mt = 0; mt < 2; mt++) {
        int oc = warpOc * 32 + mt * 16 + rowa;
        float bs0 = conv_b[oc];
        float bs1 = conv_b[oc + 8];
        float s0 = 0.f, s1 = 0.f;
#pragma unroll
        for (int nt = 0; nt < 8; nt++) {
            s0 += fmaxf(acc[nt][mt][0] + bs0, 0.f) + fmaxf(acc[nt][mt][1] + bs0, 0.f);
            s1 += fmaxf(acc[nt][mt][2] + bs1, 0.f) + fmaxf(acc[nt][mt][3] + bs1, 0.f);
        }
        s0 += __shfl_xor_sync(0xffffffffu, s0, 1);
        s0 += __shfl_xor_sync(0xffffffffu, s0, 2);
        s1 += __shfl_xor_sync(0xffffffffu, s1, 1);
        s1 += __shfl_xor_sync(0xffffffffu, s1, 2);
        if ((lane & 3) == 0) {
            int slot = rt * 4 + warpSp;
            g_partial[slot * (NIMG * COUT) + (n << 6) + oc]     = s0;
            g_partial[slot * (NIMG * COUT) + (n << 6) + oc + 8] = s1;
        }
    }
}

// ---------------------------------------------------------------------------
__global__ void reduce_nodes_kernel() {
    int i = blockIdx.x * blockDim.x + threadIdx.x;   // 32768
    float s = 0.f;
#pragma unroll
    for (int k = 0; k < NSLOT; k++) s += g_partial[k * (NIMG * COUT) + i];
    g_nodes[i] = s * (1.f / 4096.f);
}

// ---------------------------------------------------------------------------
// Graph MLP: 32 blocks x 1024 threads; 4 batches per block share one weight
// staging. Each 256-thread batch-group: 4 node-groups g x 64 hid h.
// Rank-1 decomposition: e1(i,j) = relu(a_i + c_j), a = n@W_top + b1,
// c = n@W_bot.  (proven R7, 21.1us)
// ---------------------------------------------------------------------------
#define MLP_SLAB 2064
#define MLP_DYN  ((16704 + 4 * MLP_SLAB) * 4)    // 99840 B

__global__ __launch_bounds__(1024)
void mlp_kernel(const float* __restrict__ e_w1, const float* __restrict__ e_b1,
                const float* __restrict__ e_w2, const float* __restrict__ e_b2,
                const float* __restrict__ o_w1, const float* __restrict__ o_b1,
                const float* __restrict__ o_w2, const float* __restrict__ o_b2,
                float* __restrict__ out) {
    extern __shared__ float ws[];
    float* W1  = ws;
    float* W2  = ws + 8192;
    float* OW1 = ws + 12288;
    float* OW2 = ws + 16384;
    float* B1  = ws + 16448;
    float* B2  = ws + 16512;
    float* OB1 = ws + 16576;

    const int tid  = threadIdx.x;
    const int bg   = tid >> 8;          // batch group 0..3
    const int t256 = tid & 255;
    const int g    = t256 >> 6;         // node 0..3
    const int h    = t256 & 63;
    const int b    = blockIdx.x * 4 + bg;

    float* slab = ws + 16704 + bg * MLP_SLAB;
    float* sN  = slab;
    float* sA  = slab + 256;
    float* sC  = slab + 512;
    float* sE  = slab + 768;    // [i][j][h] = [(i*4+j)*64+h]
    float* sM  = slab + 1792;
    float* red = slab + 2048;

    for (int i = tid; i < 8192; i += 1024) W1[i]  = e_w1[i];
    for (int i = tid; i < 4096; i += 1024) W2[i]  = e_w2[i];
    for (int i = tid; i < 4096; i += 1024) OW1[i] = o_w1[i];
    if (tid < 64) {
        OW2[tid] = o_w2[tid];
        B1[tid]  = e_b1[tid];
        B2[tid]  = e_b2[tid];
        OB1[tid] = o_b1[tid];
    }
    if (tid == 0) ws[16640] = o_b2[0];
    sN[g * 64 + h] = g_nodes[(g * 128 + b) * HID + h];
    __syncthreads();

    // a_g = n_g @ W_top + b1 ; c_g = n_g @ W_bot
    {
        float a0 = B1[h], a1 = 0.f, c0 = 0.f, c1 = 0.f;
#pragma unroll 8
        for (int k = 0; k < 64; k += 2) {
            float n0 = sN[g * 64 + k], n1 = sN[g * 64 + k + 1];
            a0 = fmaf(n0, W1[k * 64 + h], a0);
            a1 = fmaf(n1, W1[(k + 1) * 64 + h], a1);
            c0 = fmaf(n0, W1[(64 + k) * 64 + h], c0);
            c1 = fmaf(n1, W1[(64 + k + 1) * 64 + h], c1);
        }
        sA[g * 64 + h] = a0 + a1;
        sC[g * 64 + h] = c0 + c1;
    }
    __syncthreads();
    // e1[i=g][j][h] = relu(a_i + c_j)
    {
        float a = sA[g * 64 + h];
#pragma unroll
        for (int j = 0; j < 4; j++)
            sE[(g * 4 + j) * 64 + h] = fmaxf(a + sC[j * 64 + h], 0.f);
    }
    __syncthreads();
    // msg[j=g][h] = mean_i relu(e1[i][g] @ W2 + b2)
    {
        float m = 0.f;
        for (int i = 0; i < 4; i++) {
            float q0 = B2[h], q1 = 0.f;
            const float* e = sE + (i * 4 + g) * 64;
#pragma unroll 8
            for (int k = 0; k < 64; k += 2) {
                q0 = fmaf(e[k],     W2[k * 64 + h],       q0);
                q1 = fmaf(e[k + 1], W2[(k + 1) * 64 + h], q1);
            }
            m += fmaxf(q0 + q1, 0.f);
        }
        sM[g * 64 + h] = m * 0.25f;
    }
    __syncthreads();
    // o1 + final dot with o_w2
    {
        float q0 = OB1[h], q1 = 0.f;
#pragma unroll 8
        for (int k = 0; k < 64; k += 2) {
            q0 = fmaf(sM[g * 64 + k],     OW1[k * 64 + h],       q0);
            q1 = fmaf(sM[g * 64 + k + 1], OW1[(k + 1) * 64 + h], q1);
        }
        float v = fmaxf(q0 + q1, 0.f) * OW2[h];
#pragma unroll
        for (int m = 16; m >= 1; m >>= 1) v += __shfl_xor_sync(0xffffffffu, v, m);
        if ((t256 & 31) == 0) red[t256 >> 5] = v;
    }
    __syncthreads();
    if (t256 < 4) out[b * 4 + t256] = red[2 * t256] + red[2 * t256 + 1] + ws[16640];
}

// ---------------------------------------------------------------------------
extern "C" void kernel_launch(void* const* d_in, const int* in_sizes, int n_in,
                              void* d_out, int out_size) {
    const float* x      = (const float*)d_in[0];
    const float* conv_w = (const float*)d_in[1];
    const float* conv_b = (const float*)d_in[2];
    const float* e_w1   = (const float*)d_in[3];
    const float* e_b1   = (const float*)d_in[4];
    const float* e_w2   = (const float*)d_in[5];
    const float* e_b2   = (const float*)d_in[6];
    const float* o_w1   = (const float*)d_in[7];
    const float* o_b1   = (const float*)d_in[8];
    const float* o_w2   = (const float*)d_in[9];
    const float* o_b2   = (const float*)d_in[10];
    float* out = (float*)d_out;

    // idempotent, called every launch (no static guards per harness rules)
    cudaFuncSetAttribute(mlp_kernel,
                         cudaFuncAttributeMaxDynamicSharedMemorySize, MLP_DYN);

    prep_kernel<<<9, 256>>>(conv_w);

    dim3 grid(16, NIMG);
    conv_pool_kernel<<<grid, 256>>>(x, conv_b);

    reduce_nodes_kernel<<<(NIMG * COUT) / 256, 256>>>();

    mlp_kernel<<<32, 1024, MLP_DYN>>>(e_w1, e_b1, e_w2, e_b2,
                                      o_w1, o_b1, o_w2, o_b2, out);
}

// round 11
// speedup vs baseline: 1.6794x; 1.0106x over previous
#include <cuda_runtime.h>
#include <cuda_bf16.h>

// ---------------------------------------------------------------------------
// GraphLogitLayers: conv3x3(circular)+relu+mean-pool -> edge MLP -> node MLP.
// P=4, B=128, C=32, H=W=64, HID=64. NIMG = 512.
// NOTE: harness PTX virtual target is compute_103 (no 'a') => tcgen05
// unavailable; mma.sync implicit-GEMM conv is the ceiling (~284us HMMA floor).
// Conv: implicit-GEMM bf16 mma.sync, ldmatrix B loads, fragment-packed A,
//       warp tile 32oc x 64sp, fused bias+relu+pool partials (proven R3/R6),
//       float4 staging loads (R11).
// MLP:  32 blocks x 1024 threads, 4 batches/block, smem weight staging,
//       rank-1 edge decomposition (proven R7) + fused node reduction (R11).
// ---------------------------------------------------------------------------

#define NIMG   512
#define CIN    32
#define WW     64
#define COUT   64
#define HID    64
#define NSLOT  64          // 16 row-tiles * 4 sp-warps

// device scratch (no allocations allowed)
__device__ alignas(16) float g_partial[NSLOT * NIMG * COUT];   // 8 MB
__device__ alignas(16) uint4 g_wa[9 * 2 * 4 * 32];             // [tap][ks][mt][lane]

// ---------------------------------------------------------------------------
// prep: pack conv weights into mma A-fragment order (bf16x2 per reg, uint4 per
// lane): reg r of lane l for (tap, ks, mt):
//   m = mt*16 + (r&1)*8 + (l>>2),  k = ks*16 + (r>>1)*8 + 2*(l&3) (+1 hi half)
// ---------------------------------------------------------------------------
__global__ void prep_kernel(const float* __restrict__ w) {
    int i = blockIdx.x * blockDim.x + threadIdx.x;
    if (i >= 2304) return;
    int lane = i & 31;
    int mt   = (i >> 5) & 3;
    int ks   = (i >> 7) & 1;
    int tap  = i >> 8;
    int kh = tap / 3, kw = tap % 3;
    unsigned r[4];
#pragma unroll
    for (int rr = 0; rr < 4; rr++) {
        int m = mt * 16 + ((rr & 1) << 3) + (lane >> 2);
        int k = ks * 16 + ((rr >> 1) << 3) + ((lane & 3) << 1);
        unsigned lo = __bfloat16_as_ushort(__float2bfloat16(w[((m * CIN + k    ) * 3 + kh) * 3 + kw]));
        unsigned hi = __bfloat16_as_ushort(__float2bfloat16(w[((m * CIN + k + 1) * 3 + kh) * 3 + kw]));
        r[rr] = lo | (hi << 16);
    }
    g_wa[i] = make_uint4(r[0], r[1], r[2], r[3]);
}

// ---------------------------------------------------------------------------
__device__ __forceinline__ void mma_bf16(float* c, const unsigned* a,
                                         unsigned b0, unsigned b1) {
    asm volatile(
        "mma.sync.aligned.m16n8k16.row.col.f32.bf16.bf16.f32 "
        "{%0,%1,%2,%3}, {%4,%5,%6,%7}, {%8,%9}, {%0,%1,%2,%3};\n"
        : "+f"(c[0]), "+f"(c[1]), "+f"(c[2]), "+f"(c[3])
        : "r"(a[0]), "r"(a[1]), "r"(a[2]), "r"(a[3]), "r"(b0), "r"(b1));
}

__device__ __forceinline__ void ldsm_x4(unsigned& r0, unsigned& r1,
                                        unsigned& r2, unsigned& r3, unsigned addr) {
    asm volatile("ldmatrix.sync.aligned.m8n8.x4.shared.b16 {%0,%1,%2,%3}, [%4];\n"
                 : "=r"(r0), "=r"(r1), "=r"(r2), "=r"(r3) : "r"(addr));
}

// ---------------------------------------------------------------------------
// Fused conv + bias + relu + spatial partial-sum.
// Grid (16 row-tiles, 512 imgs), 256 threads (8 warps).
// Block tile: 4 rows x 64 cols x 64 oc. Warp: 32 oc x 64 sp (one row).
// Smem: 6 rows x 66 cols (circular halo) x ic, ic padded to ICP=40.
// Staging uses float4 global loads (12 LDG.128/thread vs 50 LDG.32).
// ---------------------------------------------------------------------------
#define ICP 40

__global__ __launch_bounds__(256, 2)
void conv_pool_kernel(const float* __restrict__ x, const float* __restrict__ conv_b) {
    __shared__ alignas(16) __nv_bfloat16 tile[6 * 66 * ICP];   // 31680 B

    const int n   = blockIdx.y;
    const int rt  = blockIdx.x;
    const int h0  = rt * 4;
    const int tid = threadIdx.x;
    const float* xb = x + ((long)n << 17);

    // interior columns: float4 over w (16 float4 per (rr,ic) row)
    for (int idx = tid; idx < 6 * CIN * 16; idx += 256) {
        int w4   = idx & 15;
        int rest = idx >> 4;
        int ic   = rest & 31;
        int rr   = rest >> 5;                        // 0..5
        int gh   = (h0 + rr + 63) & 63;
        float4 f = ((const float4*)(xb + (ic << 12) + (gh << 6)))[w4];
        __nv_bfloat16* dst = &tile[(rr * 66 + w4 * 4 + 1) * ICP + ic];
        dst[0]       = __float2bfloat16(f.x);
        dst[ICP]     = __float2bfloat16(f.y);
        dst[2 * ICP] = __float2bfloat16(f.z);
        dst[3 * ICP] = __float2bfloat16(f.w);
    }
    // circular halo columns
    for (int idx = tid; idx < 6 * CIN * 2; idx += 256) {
        int side = idx & 1;
        int rest = idx >> 1;
        int ic   = rest & 31;
        int rr   = rest >> 5;
        int gh   = (h0 + rr + 63) & 63;
        int gw   = side ? 0 : 63;
        int c    = side ? 65 : 0;
        tile[(rr * 66 + c) * ICP + ic] =
            __float2bfloat16(xb[(ic << 12) + (gh << 6) + gw]);
    }
    __syncthreads();

    const int lane   = tid & 31;
    const int warp   = tid >> 5;
    const int warpOc = warp & 1;     // 2 oc groups of 32
    const int warpSp = warp >> 1;    // 4 sp groups = block-tile rows

    unsigned sbase = (unsigned)__cvta_generic_to_shared(tile) +
                     (((warpSp * 66 + (lane & 7)) * ICP + ((lane >> 3) << 3)) << 1);

    float acc[8][2][4];
#pragma unroll
    for (int nt = 0; nt < 8; nt++)
#pragma unroll
        for (int mt = 0; mt < 2; mt++)
#pragma unroll
            for (int c = 0; c < 4; c++) acc[nt][mt][c] = 0.f;

    for (int kh = 0; kh < 3; kh++) {
        for (int kw = 0; kw < 3; kw++) {
            const int tap = kh * 3 + kw;
            uint4 a00 = g_wa[((tap * 2 + 0) * 4 + warpOc * 2 + 0) * 32 + lane];
            uint4 a01 = g_wa[((tap * 2 + 0) * 4 + warpOc * 2 + 1) * 32 + lane];
            uint4 a10 = g_wa[((tap * 2 + 1) * 4 + warpOc * 2 + 0) * 32 + lane];
            uint4 a11 = g_wa[((tap * 2 + 1) * 4 + warpOc * 2 + 1) * 32 + lane];
            unsigned tapaddr = sbase + (unsigned)(((kh * 66 + kw) * ICP) << 1);
#pragma unroll
            for (int nt = 0; nt < 8; nt++) {
                unsigned b0, b1, b2, b3;
                ldsm_x4(b0, b1, b2, b3, tapaddr + nt * (8 * ICP * 2));
                mma_bf16(acc[nt][0], (const unsigned*)&a00, b0, b1);
                mma_bf16(acc[nt][1], (const unsigned*)&a01, b0, b1);
                mma_bf16(acc[nt][0], (const unsigned*)&a10, b2, b3);
                mma_bf16(acc[nt][1], (const unsigned*)&a11, b2, b3);
            }
        }
    }

    // epilogue: bias + relu + sum over spatial, reduce over (lane&3)
    const int rowa = lane >> 2;
#pragma unroll
    for (int mt = 0; mt < 2; mt++) {
        int oc = warpOc * 32 + mt * 16 + rowa;
        float bs0 = conv_b[oc];
        float bs1 = conv_b[oc + 8];
        float s0 = 0.f, s1 = 0.f;
#pragma unroll
        for (int nt = 0; nt < 8; nt++) {
            s0 += fmaxf(acc[nt][mt][0] + bs0, 0.f) + fmaxf(acc[nt][mt][1] + bs0, 0.f);
            s1 += fmaxf(acc[nt][mt][2] + bs1, 0.f) + fmaxf(acc[nt][mt][3] + bs1, 0.f);
        }
        s0 += __shfl_xor_sync(0xffffffffu, s0, 1);
        s0 += __shfl_xor_sync(0xffffffffu, s0, 2);
        s1 += __shfl_xor_sync(0xffffffffu, s1, 1);
        s1 += __shfl_xor_sync(0xffffffffu, s1, 2);
        if ((lane & 3) == 0) {
            int slot = rt * 4 + warpSp;
            g_partial[slot * (NIMG * COUT) + (n << 6) + oc]     = s0;
            g_partial[slot * (NIMG * COUT) + (n << 6) + oc + 8] = s1;
        }
    }
}

// ---------------------------------------------------------------------------
// Graph MLP with fused node reduction. 32 blocks x 1024 threads; 4 batches
// per block share one weight staging. Each 256-thread batch-group: 4 node
// groups g x 64 hid h. Head: each thread reduces the 64 partial slots for
// its own node element (same k-order as the old reduce kernel -> bit-equal).
// Rank-1 decomposition: e1(i,j) = relu(a_i + c_j).
// ---------------------------------------------------------------------------
#define MLP_SLAB 2064
#define MLP_DYN  ((16704 + 4 * MLP_SLAB) * 4)    // 99840 B

__global__ __launch_bounds__(1024)
void mlp_kernel(const float* __restrict__ e_w1, const float* __restrict__ e_b1,
                const float* __restrict__ e_w2, const float* __restrict__ e_b2,
                const float* __restrict__ o_w1, const float* __restrict__ o_b1,
                const float* __restrict__ o_w2, const float* __restrict__ o_b2,
                float* __restrict__ out) {
    extern __shared__ float ws[];
    float* W1  = ws;
    float* W2  = ws + 8192;
    float* OW1 = ws + 12288;
    float* OW2 = ws + 16384;
    float* B1  = ws + 16448;
    float* B2  = ws + 16512;
    float* OB1 = ws + 16576;

    const int tid  = threadIdx.x;
    const int bg   = tid >> 8;          // batch group 0..3
    const int t256 = tid & 255;
    const int g    = t256 >> 6;         // node 0..3
    const int h    = t256 & 63;
    const int b    = blockIdx.x * 4 + bg;

    float* slab = ws + 16704 + bg * MLP_SLAB;
    float* sN  = slab;
    float* sA  = slab + 256;
    float* sC  = slab + 512;
    float* sE  = slab + 768;    // [i][j][h] = [(i*4+j)*64+h]
    float* sM  = slab + 1792;
    float* red = slab + 2048;

    // ---- fused node reduction: nodes[b][g][h] from 64 partial slots ----
    {
        const float* p = g_partial + (g * 128 + b) * 64 + h;
        float s = 0.f;
#pragma unroll
        for (int k = 0; k < NSLOT; k++) s += p[k * (NIMG * COUT)];
        sN[g * 64 + h] = s * (1.f / 4096.f);
    }

    // ---- weight staging: all 1024 threads ----
    for (int i = tid; i < 8192; i += 1024) W1[i]  = e_w1[i];
    for (int i = tid; i < 4096; i += 1024) W2[i]  = e_w2[i];
    for (int i = tid; i < 4096; i += 1024) OW1[i] = o_w1[i];
    if (tid < 64) {
        OW2[tid] = o_w2[tid];
        B1[tid]  = e_b1[tid];
        B2[tid]  = e_b2[tid];
        OB1[tid] = o_b1[tid];
    }
    if (tid == 0) ws[16640] = o_b2[0];
    __syncthreads();

    // a_g = n_g @ W_top + b1 ; c_g = n_g @ W_bot
    {
        float a0 = B1[h], a1 = 0.f, c0 = 0.f, c1 = 0.f;
#pragma unroll 8
        for (int k = 0; k < 64; k += 2) {
            float n0 = sN[g * 64 + k], n1 = sN[g * 64 + k + 1];
            a0 = fmaf(n0, W1[k * 64 + h], a0);
            a1 = fmaf(n1, W1[(k + 1) * 64 + h], a1);
            c0 = fmaf(n0, W1[(64 + k) * 64 + h], c0);
            c1 = fmaf(n1, W1[(64 + k + 1) * 64 + h], c1);
        }
        sA[g * 64 + h] = a0 + a1;
        sC[g * 64 + h] = c0 + c1;
    }
    __syncthreads();
    // e1[i=g][j][h] = relu(a_i + c_j)
    {
        float a = sA[g * 64 + h];
#pragma unroll
        for (int j = 0; j < 4; j++)
            sE[(g * 4 + j) * 64 + h] = fmaxf(a + sC[j * 64 + h], 0.f);
    }
    __syncthreads();
    // msg[j=g][h] = mean_i relu(e1[i][g] @ W2 + b2)
    {
        float m = 0.f;
        for (int i = 0; i < 4; i++) {
            float q0 = B2[h], q1 = 0.f;
            const float* e = sE + (i * 4 + g) * 64;
#pragma unroll 8
            for (int k = 0; k < 64; k += 2) {
                q0 = fmaf(e[k],     W2[k * 64 + h],       q0);
                q1 = fmaf(e[k + 1], W2[(k + 1) * 64 + h], q1);
            }
            m += fmaxf(q0 + q1, 0.f);
        }
        sM[g * 64 + h] = m * 0.25f;
    }
    __syncthreads();
    // o1 + final dot with o_w2
    {
        float q0 = OB1[h], q1 = 0.f;
#pragma unroll 8
        for (int k = 0; k < 64; k += 2) {
            q0 = fmaf(sM[g * 64 + k],     OW1[k * 64 + h],       q0);
            q1 = fmaf(sM[g * 64 + k + 1], OW1[(k + 1) * 64 + h], q1);
        }
        float v = fmaxf(q0 + q1, 0.f) * OW2[h];
#pragma unroll
        for (int m = 16; m >= 1; m >>= 1) v += __shfl_xor_sync(0xffffffffu, v, m);
        if ((t256 & 31) == 0) red[t256 >> 5] = v;
    }
    __syncthreads();
    if (t256 < 4) out[b * 4 + t256] = red[2 * t256] + red[2 * t256 + 1] + ws[16640];
}

// ---------------------------------------------------------------------------
extern "C" void kernel_launch(void* const* d_in, const int* in_sizes, int n_in,
                              void* d_out, int out_size) {
    const float* x      = (const float*)d_in[0];
    const float* conv_w = (const float*)d_in[1];
    const float* conv_b = (const float*)d_in[2];
    const float* e_w1   = (const float*)d_in[3];
    const float* e_b1   = (const float*)d_in[4];
    const float* e_w2   = (const float*)d_in[5];
    const float* e_b2   = (const float*)d_in[6];
    const float* o_w1   = (const float*)d_in[7];
    const float* o_b1   = (const float*)d_in[8];
    const float* o_w2   = (const float*)d_in[9];
    const float* o_b2   = (const float*)d_in[10];
    float* out = (float*)d_out;

    // idempotent, called every launch (no static guards per harness rules)
    cudaFuncSetAttribute(mlp_kernel,
                         cudaFuncAttributeMaxDynamicSharedMemorySize, MLP_DYN);

    prep_kernel<<<9, 256>>>(conv_w);

    dim3 grid(16, NIMG);
    conv_pool_kernel<<<grid, 256>>>(x, conv_b);

    mlp_kernel<<<32, 1024, MLP_DYN>>>(e_w1, e_b1, e_w2, e_b2,
                                      o_w1, o_b1, o_w2, o_b2, out);
}